// round 3
// baseline (speedup 1.0000x reference)
#include <cuda_runtime.h>
#include <math.h>

// ---------------------------------------------------------------------------
// Problem constants
//   x        [2048, 49, 512]   fp32
//   mask     [64, 49, 49]      fp32
//   bias_tab [169, 16]         fp32
//   w_qkv    [512, 1536]       fp32
//   w_proj   [512, 512]        fp32
//   out      [2048, 49, 512]   fp32
// ---------------------------------------------------------------------------

#define B_TOT   2048
#define L_TOK   49
#define C_DIM   512
#define H_HEADS 16
#define HD_DIM  32
#define ROWS    (B_TOT * L_TOK)        // 100352 = 784 * 128

// Scratch (device globals; allocation-free per harness rules)
static __device__ float g_qkv[(size_t)ROWS * 3 * C_DIM];  // 616 MB
static __device__ float g_att[(size_t)ROWS * C_DIM];      // 205 MB

__device__ __forceinline__ float f2tf32(float x) {
    unsigned u;
    asm("cvt.rna.tf32.f32 %0, %1;" : "=r"(u) : "f"(x));
    return __uint_as_float(u);
}

// ---------------------------------------------------------------------------
// tf32 tensor-core GEMM: C[M,N] = A[M,K] * B[K,N]
// BM=128, BN=128, BK=16, 256 threads (8 warps), warp grid 2(m) x 4(n),
// warp tile 64x32 via mma.sync.m16n8k8. Double-buffered smem.
//
// Shared memory holds tiles in *fragment order*:
//  A frag float4 for (blk, kkh, g, t) = [A(g,t) A(g+8,t) A(g,t+4) A(g+8,t+4)]
//    (rows relative to blk*16, k relative to kkh*8)
//    index: (((blk*2+kkh)*8+g)*4+t)*4 + comp      comp = h + 2q
//  B frag float2 for (kkh, n, t)      = [B(t,n) B(t+4,n)]
//    index: ((kkh*128 + n)*4 + t)*2 + q
// Fragment loads become LDS.128 / LDS.64, conflict-free.
// ---------------------------------------------------------------------------
__global__ __launch_bounds__(256, 2)
void gemm_tf32(const float* __restrict__ A, const float* __restrict__ B,
               float* __restrict__ C, int M, int N, int K) {
    __shared__ float As[2][2048];
    __shared__ float Bs[2][2048];

    const int tid  = threadIdx.x;
    const int lane = tid & 31;
    const int warp = tid >> 5;
    const int wm   = warp >> 2;          // 0..1
    const int wn   = warp & 3;           // 0..3
    const int g    = lane >> 2;          // 0..7
    const int t    = lane & 3;           // 0..3

    const int m0 = blockIdx.y * 128;
    const int n0 = blockIdx.x * 128;

    // Global load mapping: A rows a_m & a_m+64 (4 consecutive k),
    //                      B rows b_k & b_k+8 (4 consecutive n)
    const int a_m = tid >> 2;            // 0..63
    const int a_k = (tid & 3) * 4;       // 0,4,8,12
    const int b_k = tid >> 5;            // 0..7
    const int b_n = (tid & 31) * 4;

    const float* Ag = A + (size_t)(m0 + a_m) * K + a_k;
    const float* Bg = B + (size_t)b_k * N + n0 + b_n;

    // Permuted store offsets
    const int a_blk = a_m >> 4;                  // 0..3 (a_m+64 -> +4)
    const int a_g   = a_m & 7;
    const int a_h   = (a_m >> 3) & 1;
    const int a_kkh = a_k >> 3;
    const int a_q   = (a_k >> 2) & 1;
    const int a_comp = a_h + 2 * a_q;
    const int aoff0 = (((a_blk * 2 + a_kkh) * 8 + a_g) * 4) * 4 + a_comp;
    const int aoff1 = ((((a_blk + 4) * 2 + a_kkh) * 8 + a_g) * 4) * 4 + a_comp;

    const int b_t = b_k & 3;
    const int b_q = (b_k >> 2) & 1;
    const int boff0 = ((0 * 128 + b_n) * 4 + b_t) * 2 + b_q;   // kkh=0
    const int boff1 = ((1 * 128 + b_n) * 4 + b_t) * 2 + b_q;   // kkh=1

    float acc[16][4];
    #pragma unroll
    for (int i = 0; i < 16; ++i)
        #pragma unroll
        for (int j = 0; j < 4; ++j) acc[i][j] = 0.f;

    float4 pa0, pa1, pb0, pb1;

    // Prefetch tile 0
    pa0 = *(const float4*)(Ag);
    pa1 = *(const float4*)(Ag + (size_t)64 * K);
    pb0 = *(const float4*)(Bg);
    pb1 = *(const float4*)(Bg + (size_t)8 * N);

    // Store tile 0 into buffer 0
    {
        float* ap = &As[0][aoff0];
        ap[0] = f2tf32(pa0.x); ap[4] = f2tf32(pa0.y); ap[8] = f2tf32(pa0.z); ap[12] = f2tf32(pa0.w);
        float* ap2 = &As[0][aoff1];
        ap2[0] = f2tf32(pa1.x); ap2[4] = f2tf32(pa1.y); ap2[8] = f2tf32(pa1.z); ap2[12] = f2tf32(pa1.w);
        float* bp = &Bs[0][boff0];
        bp[0] = f2tf32(pb0.x); bp[8] = f2tf32(pb0.y); bp[16] = f2tf32(pb0.z); bp[24] = f2tf32(pb0.w);
        float* bp2 = &Bs[0][boff1];
        bp2[0] = f2tf32(pb1.x); bp2[8] = f2tf32(pb1.y); bp2[16] = f2tf32(pb1.z); bp2[24] = f2tf32(pb1.w);
    }
    __syncthreads();

    const int nK = K >> 4;
    for (int kt = 0; kt < nK; ++kt) {
        const int cur = kt & 1;
        const int nxt = cur ^ 1;

        if (kt + 1 < nK) {
            const float* An = Ag + (kt + 1) * 16;
            const float* Bn = Bg + (size_t)(kt + 1) * 16 * N;
            pa0 = *(const float4*)(An);
            pa1 = *(const float4*)(An + (size_t)64 * K);
            pb0 = *(const float4*)(Bn);
            pb1 = *(const float4*)(Bn + (size_t)8 * N);
        }

        // Compute on current buffer
        #pragma unroll
        for (int kkh = 0; kkh < 2; ++kkh) {
            float4 af[4];
            #pragma unroll
            for (int mt = 0; mt < 4; ++mt)
                af[mt] = *(const float4*)&As[cur][((((wm * 4 + mt) * 2 + kkh) * 8 + g) * 4 + t) * 4];
            float2 bf[4];
            #pragma unroll
            for (int nt = 0; nt < 4; ++nt)
                bf[nt] = *(const float2*)&Bs[cur][((kkh * 128 + wn * 32 + nt * 8 + g) * 4 + t) * 2];

            #pragma unroll
            for (int mt = 0; mt < 4; ++mt)
                #pragma unroll
                for (int nt = 0; nt < 4; ++nt) {
                    float* c = acc[mt * 4 + nt];
                    asm volatile(
                        "mma.sync.aligned.m16n8k8.row.col.f32.tf32.tf32.f32 "
                        "{%0,%1,%2,%3}, {%4,%5,%6,%7}, {%8,%9}, {%0,%1,%2,%3};\n"
                        : "+f"(c[0]), "+f"(c[1]), "+f"(c[2]), "+f"(c[3])
                        : "r"(__float_as_uint(af[mt].x)), "r"(__float_as_uint(af[mt].y)),
                          "r"(__float_as_uint(af[mt].z)), "r"(__float_as_uint(af[mt].w)),
                          "r"(__float_as_uint(bf[nt].x)), "r"(__float_as_uint(bf[nt].y)));
                }
        }

        if (kt + 1 < nK) {
            float* ap = &As[nxt][aoff0];
            ap[0] = f2tf32(pa0.x); ap[4] = f2tf32(pa0.y); ap[8] = f2tf32(pa0.z); ap[12] = f2tf32(pa0.w);
            float* ap2 = &As[nxt][aoff1];
            ap2[0] = f2tf32(pa1.x); ap2[4] = f2tf32(pa1.y); ap2[8] = f2tf32(pa1.z); ap2[12] = f2tf32(pa1.w);
            float* bp = &Bs[nxt][boff0];
            bp[0] = f2tf32(pb0.x); bp[8] = f2tf32(pb0.y); bp[16] = f2tf32(pb0.z); bp[24] = f2tf32(pb0.w);
            float* bp2 = &Bs[nxt][boff1];
            bp2[0] = f2tf32(pb1.x); bp2[8] = f2tf32(pb1.y); bp2[16] = f2tf32(pb1.z); bp2[24] = f2tf32(pb1.w);
            __syncthreads();
        }
    }

    // Epilogue
    #pragma unroll
    for (int mt = 0; mt < 4; ++mt) {
        #pragma unroll
        for (int nt = 0; nt < 4; ++nt) {
            const float* c = acc[mt * 4 + nt];
            int row = m0 + wm * 64 + mt * 16 + g;
            int col = n0 + wn * 32 + nt * 8 + t * 2;
            *(float2*)&C[(size_t)row * N + col]       = make_float2(c[0], c[1]);
            *(float2*)&C[(size_t)(row + 8) * N + col] = make_float2(c[2], c[3]);
        }
    }
}

// ---------------------------------------------------------------------------
// Attention per (window b, head h). One CTA each; grid (2048, 16).
// Qs/Ks/Vs padded to stride 36 (16B-aligned rows; strided float4 conflict-free).
// ---------------------------------------------------------------------------
__global__ __launch_bounds__(256)
void attn_kernel(const float* __restrict__ qkv, const float* __restrict__ mask,
                 const float* __restrict__ bias_table, float* __restrict__ out) {
    const int b = blockIdx.x;
    const int h = blockIdx.y;

    __shared__ float Qs[L_TOK][36];
    __shared__ float Ks[L_TOK][36];
    __shared__ float Vs[L_TOK][36];
    __shared__ float S[L_TOK][52];

    const int tid = threadIdx.x;
    const float* base = qkv + (size_t)b * L_TOK * (3 * C_DIM) + h * HD_DIM;

    for (int i = tid; i < L_TOK * 8; i += 256) {
        int l  = i >> 3;
        int d4 = (i & 7) * 4;
        const float* p = base + (size_t)l * (3 * C_DIM) + d4;
        *(float4*)&Qs[l][d4] = *(const float4*)(p);
        *(float4*)&Ks[l][d4] = *(const float4*)(p + C_DIM);
        *(float4*)&Vs[l][d4] = *(const float4*)(p + 2 * C_DIM);
    }
    __syncthreads();

    const int   win   = b & 63;
    const float scale = 0.1767766952966369f;  // 32^-0.5

    for (int e = tid; e < L_TOK * L_TOK; e += 256) {
        int l = e / L_TOK;
        int m = e - l * L_TOK;
        float s = 0.f;
        #pragma unroll
        for (int d4 = 0; d4 < HD_DIM; d4 += 4) {
            float4 qa = *(const float4*)&Qs[l][d4];
            float4 kb = *(const float4*)&Ks[m][d4];
            s = fmaf(qa.x, kb.x, s);
            s = fmaf(qa.y, kb.y, s);
            s = fmaf(qa.z, kb.z, s);
            s = fmaf(qa.w, kb.w, s);
        }
        int lh = l / 7, lw = l - lh * 7;
        int mh = m / 7, mw = m - mh * 7;
        int ri = (lh - mh + 6) * 13 + (lw - mw + 6);
        s = s * scale + bias_table[ri * H_HEADS + h]
                      + mask[((size_t)win * L_TOK + l) * L_TOK + m];
        S[l][m] = s;
    }
    __syncthreads();

    const int warp = tid >> 5;
    const int lane = tid & 31;
    for (int l = warp; l < L_TOK; l += 8) {
        float v0 = S[l][lane];
        float v1 = (lane < L_TOK - 32) ? S[l][lane + 32] : -1e30f;
        float mx = fmaxf(v0, v1);
        #pragma unroll
        for (int o = 16; o > 0; o >>= 1) mx = fmaxf(mx, __shfl_xor_sync(0xffffffffu, mx, o));
        float e0 = __expf(v0 - mx);
        float e1 = (lane < L_TOK - 32) ? __expf(v1 - mx) : 0.f;
        float sm = e0 + e1;
        #pragma unroll
        for (int o = 16; o > 0; o >>= 1) sm += __shfl_xor_sync(0xffffffffu, sm, o);
        float inv = 1.f / sm;
        S[l][lane] = e0 * inv;
        if (lane < L_TOK - 32) S[l][lane + 32] = e1 * inv;
    }
    __syncthreads();

    float* ob = out + (size_t)b * L_TOK * C_DIM + h * HD_DIM;
    for (int e = tid; e < L_TOK * HD_DIM; e += 256) {
        int l = e >> 5;
        int d = e & 31;
        float s = 0.f;
        #pragma unroll
        for (int m = 0; m < L_TOK; ++m) s = fmaf(S[l][m], Vs[m][d], s);
        ob[(size_t)l * C_DIM + d] = s;
    }
}

// ---------------------------------------------------------------------------
// kernel_launch
// ---------------------------------------------------------------------------
extern "C" void kernel_launch(void* const* d_in, const int* in_sizes, int n_in,
                              void* d_out, int out_size) {
    const float* x     = (const float*)d_in[0];
    const float* mask  = (const float*)d_in[1];
    const float* bias  = (const float*)d_in[2];
    const float* wqkv  = (const float*)d_in[3];
    const float* wproj = (const float*)d_in[4];
    float*       out   = (float*)d_out;

    float* qkv = nullptr;
    float* att = nullptr;
    cudaGetSymbolAddress((void**)&qkv, g_qkv);
    cudaGetSymbolAddress((void**)&att, g_att);

    // 1) QKV projection: [100352, 512] x [512, 1536]  (tf32 tensor cores)
    gemm_tf32<<<dim3(1536 / 128, ROWS / 128), 256>>>(x, wqkv, qkv, ROWS, 3 * C_DIM, C_DIM);

    // 2) Windowed attention per (window, head)
    attn_kernel<<<dim3(B_TOT, H_HEADS), 256>>>(qkv, mask, bias, att);

    // 3) Output projection: [100352, 512] x [512, 512]  (tf32 tensor cores)
    gemm_tf32<<<dim3(C_DIM / 128, ROWS / 128), 256>>>(att, wproj, out, ROWS, C_DIM, C_DIM);
}

// round 4
// speedup vs baseline: 2.3782x; 2.3782x over previous
#include <cuda_runtime.h>
#include <math.h>
#include <stdint.h>

// ---------------------------------------------------------------------------
// Problem constants
//   x        [2048, 49, 512]   fp32
//   mask     [64, 49, 49]      fp32
//   bias_tab [169, 16]         fp32
//   w_qkv    [512, 1536]       fp32
//   w_proj   [512, 512]        fp32
//   out      [2048, 49, 512]   fp32
// ---------------------------------------------------------------------------

#define B_TOT   2048
#define L_TOK   49
#define C_DIM   512
#define H_HEADS 16
#define HD_DIM  32
#define ROWS    (B_TOT * L_TOK)        // 100352 = 784 * 128

// Scratch (device globals; allocation-free per harness rules)
static __device__ float g_qkv[(size_t)ROWS * 3 * C_DIM];   // 616 MB
static __device__ float g_att[(size_t)ROWS * C_DIM];       // 205 MB
static __device__ float g_wqkv_t[3 * C_DIM * C_DIM];       // [1536][512]
static __device__ float g_wproj_t[C_DIM * C_DIM];          // [512][512]

__device__ __forceinline__ float f2tf32(float x) {
    unsigned u;
    asm("cvt.rna.tf32.f32 %0, %1;" : "=r"(u) : "f"(x));
    return __uint_as_float(u);
}

__device__ __forceinline__ void ldsm_x4(uint32_t addr, uint32_t& r0, uint32_t& r1,
                                        uint32_t& r2, uint32_t& r3) {
    asm volatile("ldmatrix.sync.aligned.m8n8.x4.shared.b16 {%0,%1,%2,%3}, [%4];"
                 : "=r"(r0), "=r"(r1), "=r"(r2), "=r"(r3) : "r"(addr));
}

// ---------------------------------------------------------------------------
// Weight transpose: Wt[n][k] = W[k][n].  grid(N/32, K/32), block(32, 8)
// ---------------------------------------------------------------------------
__global__ void transpose_k(const float* __restrict__ W, float* __restrict__ Wt,
                            int Kdim, int Ndim) {
    __shared__ float t[32][33];
    const int n0 = blockIdx.x * 32, k0 = blockIdx.y * 32;
    const int x = threadIdx.x, y = threadIdx.y;
    #pragma unroll
    for (int i = 0; i < 32; i += 8)
        t[y + i][x] = W[(size_t)(k0 + y + i) * Ndim + n0 + x];
    __syncthreads();
    #pragma unroll
    for (int i = 0; i < 32; i += 8)
        Wt[(size_t)(n0 + y + i) * Kdim + k0 + x] = t[x][y + i];
}

// ---------------------------------------------------------------------------
// tf32 tensor-core GEMM: C[M,N] = A[M,K] * Bt[N,K]^T
// BM=128, BN=128, BK=16, 256 threads (8 warps), warp grid 2(m) x 4(n),
// warp tile 64x32 via mma.sync.m16n8k8. Double-buffered smem, ldmatrix loads.
//
// Smem tiles: [128 rows][16 floats] = [128][4 float4], XOR-swizzled:
//   f4_index(row, c) = row*4 + (c ^ ((row>>1)&3))
// Conflict-free for both STS.128 stores and ldmatrix reads (see analysis).
// ---------------------------------------------------------------------------
__global__ __launch_bounds__(256, 2)
void gemm_tf32(const float* __restrict__ A, const float* __restrict__ Bt,
               float* __restrict__ C, int M, int N, int K) {
    __shared__ float As[2][2048];
    __shared__ float Bs[2][2048];

    const int tid  = threadIdx.x;
    const int lane = tid & 31;
    const int warp = tid >> 5;
    const int wm   = warp >> 2;          // 0..1
    const int wn   = warp & 3;           // 0..3

    const int m0 = blockIdx.y * 128;
    const int n0 = blockIdx.x * 128;

    // ---- global load mapping (same for A and B): row = tid>>2 (+64), 4 k's
    const int r_g = tid >> 2;            // 0..63
    const int q   = tid & 3;             // float4 column

    const float* Ag  = A  + (size_t)(m0 + r_g) * K + q * 4;
    const float* Ag2 = Ag + (size_t)64 * K;
    const float* Bg  = Bt + (size_t)(n0 + r_g) * K + q * 4;
    const float* Bg2 = Bg + (size_t)64 * K;

    // ---- swizzled store offsets (float index); rows r_g and r_g+64 share swizzle
    const int st0 = (r_g * 4 + (q ^ ((r_g >> 1) & 3))) * 4;
    const int st1 = st0 + 64 * 4 * 4;

    // ---- ldmatrix lane constants
    const int swz   = (lane >> 1) & 3;            // ((lane&7)>>1)&3
    const int aRow  = wm * 64 + (lane & 7) + ((lane >> 3) & 1) * 8;
    const int aCol  = lane >> 4;                  // k-half select
    const int bRow  = wn * 32 + (lane & 7) + (lane >> 4) * 8;
    const int bHalf = (lane >> 3) & 1;

    const uint32_t as0 = (uint32_t)__cvta_generic_to_shared(&As[0][0]);
    const uint32_t as1 = (uint32_t)__cvta_generic_to_shared(&As[1][0]);
    const uint32_t bs0 = (uint32_t)__cvta_generic_to_shared(&Bs[0][0]);
    const uint32_t bs1 = (uint32_t)__cvta_generic_to_shared(&Bs[1][0]);

    float acc[16][4];
    #pragma unroll
    for (int i = 0; i < 16; ++i)
        #pragma unroll
        for (int j = 0; j < 4; ++j) acc[i][j] = 0.f;

    float4 pa0, pa1, pb0, pb1;

    // Prefetch + store tile 0
    pa0 = *(const float4*)(Ag);
    pa1 = *(const float4*)(Ag2);
    pb0 = *(const float4*)(Bg);
    pb1 = *(const float4*)(Bg2);
    {
        *(float4*)&As[0][st0] = make_float4(f2tf32(pa0.x), f2tf32(pa0.y), f2tf32(pa0.z), f2tf32(pa0.w));
        *(float4*)&As[0][st1] = make_float4(f2tf32(pa1.x), f2tf32(pa1.y), f2tf32(pa1.z), f2tf32(pa1.w));
        *(float4*)&Bs[0][st0] = make_float4(f2tf32(pb0.x), f2tf32(pb0.y), f2tf32(pb0.z), f2tf32(pb0.w));
        *(float4*)&Bs[0][st1] = make_float4(f2tf32(pb1.x), f2tf32(pb1.y), f2tf32(pb1.z), f2tf32(pb1.w));
    }
    __syncthreads();

    const int nK = K >> 4;
    for (int kt = 0; kt < nK; ++kt) {
        const int cur = kt & 1;

        if (kt + 1 < nK) {
            pa0 = *(const float4*)(Ag  + (kt + 1) * 16);
            pa1 = *(const float4*)(Ag2 + (kt + 1) * 16);
            pb0 = *(const float4*)(Bg  + (kt + 1) * 16);
            pb1 = *(const float4*)(Bg2 + (kt + 1) * 16);
        }

        const uint32_t aB = cur ? as1 : as0;
        const uint32_t bB = cur ? bs1 : bs0;

        #pragma unroll
        for (int kkh = 0; kkh < 2; ++kkh) {
            uint32_t af[4][4];
            #pragma unroll
            for (int mt = 0; mt < 4; ++mt) {
                uint32_t addr = aB + (uint32_t)(((aRow + mt * 16) * 4 +
                                 ((kkh * 2 + aCol) ^ swz)) * 16);
                ldsm_x4(addr, af[mt][0], af[mt][1], af[mt][2], af[mt][3]);
            }
            uint32_t bf[2][4];
            #pragma unroll
            for (int ntp = 0; ntp < 2; ++ntp) {
                uint32_t addr = bB + (uint32_t)(((bRow + ntp * 16) * 4 +
                                 ((kkh * 2 + bHalf) ^ swz)) * 16);
                ldsm_x4(addr, bf[ntp][0], bf[ntp][1], bf[ntp][2], bf[ntp][3]);
            }
            #pragma unroll
            for (int mt = 0; mt < 4; ++mt)
                #pragma unroll
                for (int nt = 0; nt < 4; ++nt) {
                    float* c = acc[mt * 4 + nt];
                    asm volatile(
                        "mma.sync.aligned.m16n8k8.row.col.f32.tf32.tf32.f32 "
                        "{%0,%1,%2,%3}, {%4,%5,%6,%7}, {%8,%9}, {%0,%1,%2,%3};\n"
                        : "+f"(c[0]), "+f"(c[1]), "+f"(c[2]), "+f"(c[3])
                        : "r"(af[mt][0]), "r"(af[mt][1]), "r"(af[mt][2]), "r"(af[mt][3]),
                          "r"(bf[nt >> 1][(nt & 1) * 2]), "r"(bf[nt >> 1][(nt & 1) * 2 + 1]));
                }
        }

        if (kt + 1 < nK) {
            const int nxt = cur ^ 1;
            float* ad = nxt ? As[1] : As[0];
            float* bd = nxt ? Bs[1] : Bs[0];
            *(float4*)&ad[st0] = make_float4(f2tf32(pa0.x), f2tf32(pa0.y), f2tf32(pa0.z), f2tf32(pa0.w));
            *(float4*)&ad[st1] = make_float4(f2tf32(pa1.x), f2tf32(pa1.y), f2tf32(pa1.z), f2tf32(pa1.w));
            *(float4*)&bd[st0] = make_float4(f2tf32(pb0.x), f2tf32(pb0.y), f2tf32(pb0.z), f2tf32(pb0.w));
            *(float4*)&bd[st1] = make_float4(f2tf32(pb1.x), f2tf32(pb1.y), f2tf32(pb1.z), f2tf32(pb1.w));
            __syncthreads();
        }
    }

    // Epilogue
    const int g = lane >> 2;
    const int t = lane & 3;
    #pragma unroll
    for (int mt = 0; mt < 4; ++mt) {
        #pragma unroll
        for (int nt = 0; nt < 4; ++nt) {
            const float* c = acc[mt * 4 + nt];
            int row = m0 + wm * 64 + mt * 16 + g;
            int col = n0 + wn * 32 + nt * 8 + t * 2;
            *(float2*)&C[(size_t)row * N + col]       = make_float2(c[0], c[1]);
            *(float2*)&C[(size_t)(row + 8) * N + col] = make_float2(c[2], c[3]);
        }
    }
}

// ---------------------------------------------------------------------------
// Attention per (window b, head h). One CTA each; grid (2048, 16).
// ---------------------------------------------------------------------------
__global__ __launch_bounds__(256)
void attn_kernel(const float* __restrict__ qkv, const float* __restrict__ mask,
                 const float* __restrict__ bias_table, float* __restrict__ out) {
    const int b = blockIdx.x;
    const int h = blockIdx.y;

    __shared__ float Qs[L_TOK][36];
    __shared__ float Ks[L_TOK][36];
    __shared__ float Vs[L_TOK][36];
    __shared__ float S[L_TOK][52];

    const int tid = threadIdx.x;
    const float* base = qkv + (size_t)b * L_TOK * (3 * C_DIM) + h * HD_DIM;

    for (int i = tid; i < L_TOK * 8; i += 256) {
        int l  = i >> 3;
        int d4 = (i & 7) * 4;
        const float* p = base + (size_t)l * (3 * C_DIM) + d4;
        *(float4*)&Qs[l][d4] = *(const float4*)(p);
        *(float4*)&Ks[l][d4] = *(const float4*)(p + C_DIM);
        *(float4*)&Vs[l][d4] = *(const float4*)(p + 2 * C_DIM);
    }
    __syncthreads();

    const int   win   = b & 63;
    const float scale = 0.1767766952966369f;  // 32^-0.5

    for (int e = tid; e < L_TOK * L_TOK; e += 256) {
        int l = e / L_TOK;
        int m = e - l * L_TOK;
        float s = 0.f;
        #pragma unroll
        for (int d4 = 0; d4 < HD_DIM; d4 += 4) {
            float4 qa = *(const float4*)&Qs[l][d4];
            float4 kb = *(const float4*)&Ks[m][d4];
            s = fmaf(qa.x, kb.x, s);
            s = fmaf(qa.y, kb.y, s);
            s = fmaf(qa.z, kb.z, s);
            s = fmaf(qa.w, kb.w, s);
        }
        int lh = l / 7, lw = l - lh * 7;
        int mh = m / 7, mw = m - mh * 7;
        int ri = (lh - mh + 6) * 13 + (lw - mw + 6);
        s = s * scale + bias_table[ri * H_HEADS + h]
                      + mask[((size_t)win * L_TOK + l) * L_TOK + m];
        S[l][m] = s;
    }
    __syncthreads();

    const int warp = tid >> 5;
    const int lane = tid & 31;
    for (int l = warp; l < L_TOK; l += 8) {
        float v0 = S[l][lane];
        float v1 = (lane < L_TOK - 32) ? S[l][lane + 32] : -1e30f;
        float mx = fmaxf(v0, v1);
        #pragma unroll
        for (int o = 16; o > 0; o >>= 1) mx = fmaxf(mx, __shfl_xor_sync(0xffffffffu, mx, o));
        float e0 = __expf(v0 - mx);
        float e1 = (lane < L_TOK - 32) ? __expf(v1 - mx) : 0.f;
        float sm = e0 + e1;
        #pragma unroll
        for (int o = 16; o > 0; o >>= 1) sm += __shfl_xor_sync(0xffffffffu, sm, o);
        float inv = 1.f / sm;
        S[l][lane] = e0 * inv;
        if (lane < L_TOK - 32) S[l][lane + 32] = e1 * inv;
    }
    __syncthreads();

    float* ob = out + (size_t)b * L_TOK * C_DIM + h * HD_DIM;
    for (int e = tid; e < L_TOK * HD_DIM; e += 256) {
        int l = e >> 5;
        int d = e & 31;
        float s = 0.f;
        #pragma unroll
        for (int m = 0; m < L_TOK; ++m) s = fmaf(S[l][m], Vs[m][d], s);
        ob[(size_t)l * C_DIM + d] = s;
    }
}

// ---------------------------------------------------------------------------
// kernel_launch
// ---------------------------------------------------------------------------
extern "C" void kernel_launch(void* const* d_in, const int* in_sizes, int n_in,
                              void* d_out, int out_size) {
    const float* x     = (const float*)d_in[0];
    const float* mask  = (const float*)d_in[1];
    const float* bias  = (const float*)d_in[2];
    const float* wqkv  = (const float*)d_in[3];
    const float* wproj = (const float*)d_in[4];
    float*       out   = (float*)d_out;

    float *qkv = nullptr, *att = nullptr, *wqkv_t = nullptr, *wproj_t = nullptr;
    cudaGetSymbolAddress((void**)&qkv, g_qkv);
    cudaGetSymbolAddress((void**)&att, g_att);
    cudaGetSymbolAddress((void**)&wqkv_t, g_wqkv_t);
    cudaGetSymbolAddress((void**)&wproj_t, g_wproj_t);

    // 0) Transpose weights to n-major for ldmatrix-friendly B tiles
    transpose_k<<<dim3(1536 / 32, 512 / 32), dim3(32, 8)>>>(wqkv, wqkv_t, C_DIM, 3 * C_DIM);
    transpose_k<<<dim3(512 / 32, 512 / 32), dim3(32, 8)>>>(wproj, wproj_t, C_DIM, C_DIM);

    // 1) QKV projection: [100352, 512] x [512, 1536]  (tf32 tensor cores)
    gemm_tf32<<<dim3(1536 / 128, ROWS / 128), 256>>>(x, wqkv_t, qkv, ROWS, 3 * C_DIM, C_DIM);

    // 2) Windowed attention per (window, head)
    attn_kernel<<<dim3(B_TOT, H_HEADS), 256>>>(qkv, mask, bias, att);

    // 3) Output projection: [100352, 512] x [512, 512]  (tf32 tensor cores)
    gemm_tf32<<<dim3(C_DIM / 128, ROWS / 128), 256>>>(att, wproj_t, out, ROWS, C_DIM, C_DIM);
}

// round 5
// speedup vs baseline: 3.1957x; 1.3438x over previous
#include <cuda_runtime.h>
#include <math.h>
#include <stdint.h>

// ---------------------------------------------------------------------------
// Problem constants
//   x        [2048, 49, 512]   fp32
//   mask     [64, 49, 49]      fp32
//   bias_tab [169, 16]         fp32
//   w_qkv    [512, 1536]       fp32
//   w_proj   [512, 512]        fp32
//   out      [2048, 49, 512]   fp32
// ---------------------------------------------------------------------------

#define B_TOT   2048
#define L_TOK   49
#define C_DIM   512
#define H_HEADS 16
#define HD_DIM  32
#define ROWS    (B_TOT * L_TOK)        // 100352 = 784 * 128

// Scratch (device globals; allocation-free per harness rules)
static __device__ float g_qkv[(size_t)ROWS * 3 * C_DIM];   // 616 MB
static __device__ float g_att[(size_t)ROWS * C_DIM];       // 205 MB
static __device__ float g_wqkv_t[3 * C_DIM * C_DIM];       // [1536][512]
static __device__ float g_wproj_t[C_DIM * C_DIM];          // [512][512]

__device__ __forceinline__ float f2tf32(float x) {
    unsigned u;
    asm("cvt.rna.tf32.f32 %0, %1;" : "=r"(u) : "f"(x));
    return __uint_as_float(u);
}

__device__ __forceinline__ void ldsm_x4(uint32_t addr, uint32_t& r0, uint32_t& r1,
                                        uint32_t& r2, uint32_t& r3) {
    asm volatile("ldmatrix.sync.aligned.m8n8.x4.shared.b16 {%0,%1,%2,%3}, [%4];"
                 : "=r"(r0), "=r"(r1), "=r"(r2), "=r"(r3) : "r"(addr));
}

#define MMA_TF32(c, a0, a1, a2, a3, b0, b1)                                     \
    asm volatile(                                                               \
        "mma.sync.aligned.m16n8k8.row.col.f32.tf32.tf32.f32 "                   \
        "{%0,%1,%2,%3}, {%4,%5,%6,%7}, {%8,%9}, {%0,%1,%2,%3};\n"               \
        : "+f"((c)[0]), "+f"((c)[1]), "+f"((c)[2]), "+f"((c)[3])                \
        : "r"(a0), "r"(a1), "r"(a2), "r"(a3), "r"(b0), "r"(b1))

// ---------------------------------------------------------------------------
// Weight transpose: Wt[n][k] = W[k][n].  grid(N/32, K/32), block(32, 8)
// ---------------------------------------------------------------------------
__global__ void transpose_k(const float* __restrict__ W, float* __restrict__ Wt,
                            int Kdim, int Ndim) {
    __shared__ float t[32][33];
    const int n0 = blockIdx.x * 32, k0 = blockIdx.y * 32;
    const int x = threadIdx.x, y = threadIdx.y;
    #pragma unroll
    for (int i = 0; i < 32; i += 8)
        t[y + i][x] = W[(size_t)(k0 + y + i) * Ndim + n0 + x];
    __syncthreads();
    #pragma unroll
    for (int i = 0; i < 32; i += 8)
        Wt[(size_t)(n0 + y + i) * Kdim + k0 + x] = t[x][y + i];
}

// ---------------------------------------------------------------------------
// tf32 tensor-core GEMM: C[M,N] = A[M,K] * Bt[N,K]^T   (same as round 4)
// ---------------------------------------------------------------------------
__global__ __launch_bounds__(256, 2)
void gemm_tf32(const float* __restrict__ A, const float* __restrict__ Bt,
               float* __restrict__ C, int M, int N, int K) {
    __shared__ float As[2][2048];
    __shared__ float Bs[2][2048];

    const int tid  = threadIdx.x;
    const int lane = tid & 31;
    const int warp = tid >> 5;
    const int wm   = warp >> 2;
    const int wn   = warp & 3;

    const int m0 = blockIdx.y * 128;
    const int n0 = blockIdx.x * 128;

    const int r_g = tid >> 2;
    const int q   = tid & 3;

    const float* Ag  = A  + (size_t)(m0 + r_g) * K + q * 4;
    const float* Ag2 = Ag + (size_t)64 * K;
    const float* Bg  = Bt + (size_t)(n0 + r_g) * K + q * 4;
    const float* Bg2 = Bg + (size_t)64 * K;

    const int st0 = (r_g * 4 + (q ^ ((r_g >> 1) & 3))) * 4;
    const int st1 = st0 + 64 * 4 * 4;

    const int swz   = (lane >> 1) & 3;
    const int aRow  = wm * 64 + (lane & 7) + ((lane >> 3) & 1) * 8;
    const int aCol  = lane >> 4;
    const int bRow  = wn * 32 + (lane & 7) + (lane >> 4) * 8;
    const int bHalf = (lane >> 3) & 1;

    const uint32_t as0 = (uint32_t)__cvta_generic_to_shared(&As[0][0]);
    const uint32_t as1 = (uint32_t)__cvta_generic_to_shared(&As[1][0]);
    const uint32_t bs0 = (uint32_t)__cvta_generic_to_shared(&Bs[0][0]);
    const uint32_t bs1 = (uint32_t)__cvta_generic_to_shared(&Bs[1][0]);

    float acc[16][4];
    #pragma unroll
    for (int i = 0; i < 16; ++i)
        #pragma unroll
        for (int j = 0; j < 4; ++j) acc[i][j] = 0.f;

    float4 pa0, pa1, pb0, pb1;

    pa0 = *(const float4*)(Ag);
    pa1 = *(const float4*)(Ag2);
    pb0 = *(const float4*)(Bg);
    pb1 = *(const float4*)(Bg2);
    {
        *(float4*)&As[0][st0] = make_float4(f2tf32(pa0.x), f2tf32(pa0.y), f2tf32(pa0.z), f2tf32(pa0.w));
        *(float4*)&As[0][st1] = make_float4(f2tf32(pa1.x), f2tf32(pa1.y), f2tf32(pa1.z), f2tf32(pa1.w));
        *(float4*)&Bs[0][st0] = make_float4(f2tf32(pb0.x), f2tf32(pb0.y), f2tf32(pb0.z), f2tf32(pb0.w));
        *(float4*)&Bs[0][st1] = make_float4(f2tf32(pb1.x), f2tf32(pb1.y), f2tf32(pb1.z), f2tf32(pb1.w));
    }
    __syncthreads();

    const int nK = K >> 4;
    for (int kt = 0; kt < nK; ++kt) {
        const int cur = kt & 1;

        if (kt + 1 < nK) {
            pa0 = *(const float4*)(Ag  + (kt + 1) * 16);
            pa1 = *(const float4*)(Ag2 + (kt + 1) * 16);
            pb0 = *(const float4*)(Bg  + (kt + 1) * 16);
            pb1 = *(const float4*)(Bg2 + (kt + 1) * 16);
        }

        const uint32_t aB = cur ? as1 : as0;
        const uint32_t bB = cur ? bs1 : bs0;

        #pragma unroll
        for (int kkh = 0; kkh < 2; ++kkh) {
            uint32_t af[4][4];
            #pragma unroll
            for (int mt = 0; mt < 4; ++mt) {
                uint32_t addr = aB + (uint32_t)(((aRow + mt * 16) * 4 +
                                 ((kkh * 2 + aCol) ^ swz)) * 16);
                ldsm_x4(addr, af[mt][0], af[mt][1], af[mt][2], af[mt][3]);
            }
            uint32_t bf[2][4];
            #pragma unroll
            for (int ntp = 0; ntp < 2; ++ntp) {
                uint32_t addr = bB + (uint32_t)(((bRow + ntp * 16) * 4 +
                                 ((kkh * 2 + bHalf) ^ swz)) * 16);
                ldsm_x4(addr, bf[ntp][0], bf[ntp][1], bf[ntp][2], bf[ntp][3]);
            }
            #pragma unroll
            for (int mt = 0; mt < 4; ++mt)
                #pragma unroll
                for (int nt = 0; nt < 4; ++nt)
                    MMA_TF32(acc[mt * 4 + nt],
                             af[mt][0], af[mt][1], af[mt][2], af[mt][3],
                             bf[nt >> 1][(nt & 1) * 2], bf[nt >> 1][(nt & 1) * 2 + 1]);
        }

        if (kt + 1 < nK) {
            const int nxt = cur ^ 1;
            float* ad = nxt ? As[1] : As[0];
            float* bd = nxt ? Bs[1] : Bs[0];
            *(float4*)&ad[st0] = make_float4(f2tf32(pa0.x), f2tf32(pa0.y), f2tf32(pa0.z), f2tf32(pa0.w));
            *(float4*)&ad[st1] = make_float4(f2tf32(pa1.x), f2tf32(pa1.y), f2tf32(pa1.z), f2tf32(pa1.w));
            *(float4*)&bd[st0] = make_float4(f2tf32(pb0.x), f2tf32(pb0.y), f2tf32(pb0.z), f2tf32(pb0.w));
            *(float4*)&bd[st1] = make_float4(f2tf32(pb1.x), f2tf32(pb1.y), f2tf32(pb1.z), f2tf32(pb1.w));
            __syncthreads();
        }
    }

    const int g = lane >> 2;
    const int t = lane & 3;
    #pragma unroll
    for (int mt = 0; mt < 4; ++mt) {
        #pragma unroll
        for (int nt = 0; nt < 4; ++nt) {
            const float* c = acc[mt * 4 + nt];
            int row = m0 + wm * 64 + mt * 16 + g;
            int col = n0 + wn * 32 + nt * 8 + t * 2;
            *(float2*)&C[(size_t)row * N + col]       = make_float2(c[0], c[1]);
            *(float2*)&C[(size_t)(row + 8) * N + col] = make_float2(c[2], c[3]);
        }
    }
}

// ---------------------------------------------------------------------------
// Tensor-core attention. One CTA per (window b, head h); 128 threads, 4 warps.
// Warp w owns output rows [w*16, w*16+16).
//
// Smem (floats):
//   Qs  [64][32]  swizzled f4: idx = row*8  + (c ^ (row&7))     OFF 0
//   Ks  [64][32]  same swizzle                                  OFF 2048
//   Vt  [32][64]  (V transposed, d-major) idx = row*16 + (c^(row&7))  OFF 4096
//   S   [64][68]  unswizzled, stride 17 f4 (17%8==1 -> ldmatrix OK)   OFF 6144
//   bias_s [169]                                                OFF 10496
// ---------------------------------------------------------------------------
#define AQ_OFF 0
#define AK_OFF 2048
#define AV_OFF 4096
#define AS_OFF 6144
#define AB_OFF 10496
#define ASM_TOT 10668

__global__ __launch_bounds__(128)
void attn_tc(const float* __restrict__ qkv, const float* __restrict__ mask,
             const float* __restrict__ bias_table, float* __restrict__ out) {
    __shared__ float sm[ASM_TOT];

    const int b = blockIdx.x, h = blockIdx.y;
    const int tid = threadIdx.x, lane = tid & 31, w = tid >> 5;

    const float* base = qkv + (size_t)b * L_TOK * 1536 + h * HD_DIM;

    // Phase 1: load Q,K (tf32-rounded, zero-padded rows 49..63); zero Vt
    for (int i = tid; i < 512; i += 128) {
        int l = i >> 3, c4 = i & 7;
        float4 z = make_float4(0.f, 0.f, 0.f, 0.f);
        float4 qv = z, kv = z;
        if (l < L_TOK) {
            const float* p = base + (size_t)l * 1536 + c4 * 4;
            float4 qr = *(const float4*)p;
            float4 kr = *(const float4*)(p + C_DIM);
            qv = make_float4(f2tf32(qr.x), f2tf32(qr.y), f2tf32(qr.z), f2tf32(qr.w));
            kv = make_float4(f2tf32(kr.x), f2tf32(kr.y), f2tf32(kr.z), f2tf32(kr.w));
        }
        int dst = (l * 8 + (c4 ^ (l & 7))) * 4;
        *(float4*)&sm[AQ_OFF + dst] = qv;
        *(float4*)&sm[AK_OFF + dst] = kv;
        *(float4*)&sm[AV_OFF + i * 4] = z;
    }
    __syncthreads();

    // Phase 2: V transpose into Vt; bias column for head h
    for (int i = tid; i < L_TOK * 8; i += 128) {
        int l = i >> 3, c4 = i & 7;
        float4 v = *(const float4*)(base + (size_t)l * 1536 + 2 * C_DIM + c4 * 4);
        int cl = l >> 2, lo = l & 3;
        float vv[4] = {v.x, v.y, v.z, v.w};
        #pragma unroll
        for (int j = 0; j < 4; ++j) {
            int d = c4 * 4 + j;
            sm[AV_OFF + (d * 16 + (cl ^ (d & 7))) * 4 + lo] = f2tf32(vv[j]);
        }
    }
    for (int i = tid; i < 169; i += 128) sm[AB_OFF + i] = bias_table[i * H_HEADS + h];
    __syncthreads();

    const uint32_t sbase = (uint32_t)__cvta_generic_to_shared(sm);

    // ldmatrix lane constants (validated fragment maps from gemm_tf32)
    const int aRow  = w * 16 + (lane & 7) + ((lane >> 3) & 1) * 8;
    const int aCol  = lane >> 4;
    const int bRowB = (lane & 7) + (lane >> 4) * 8;
    const int bHalf = (lane >> 3) & 1;

    // ---- QK^T: S[w*16..+16][0..55] ----
    float sacc[7][4];
    #pragma unroll
    for (int j = 0; j < 7; ++j)
        #pragma unroll
        for (int r = 0; r < 4; ++r) sacc[j][r] = 0.f;

    #pragma unroll
    for (int ks = 0; ks < 4; ++ks) {
        uint32_t a[4];
        ldsm_x4(sbase + AQ_OFF * 4 +
                (uint32_t)((aRow * 8 + ((2 * ks + aCol) ^ (aRow & 7))) * 16),
                a[0], a[1], a[2], a[3]);
        uint32_t bf[4][4];
        #pragma unroll
        for (int ntp = 0; ntp < 4; ++ntp) {
            int row = bRowB + ntp * 16;
            ldsm_x4(sbase + AK_OFF * 4 +
                    (uint32_t)((row * 8 + ((2 * ks + bHalf) ^ (row & 7))) * 16),
                    bf[ntp][0], bf[ntp][1], bf[ntp][2], bf[ntp][3]);
        }
        #pragma unroll
        for (int nt = 0; nt < 7; ++nt)
            MMA_TF32(sacc[nt], a[0], a[1], a[2], a[3],
                     bf[nt >> 1][(nt & 1) * 2], bf[nt >> 1][(nt & 1) * 2 + 1]);
    }

    // ---- scale + bias + mask + softmax (register resident) ----
    const int g = lane >> 2, t = lane & 3;
    const int l0 = w * 16 + g, l1 = l0 + 8;
    const int win = b & 63;
    const bool v0 = (l0 < L_TOK), v1 = (l1 < L_TOK);
    const int lh0 = l0 / 7, lw0 = l0 - lh0 * 7;
    const int lh1 = l1 / 7, lw1 = l1 - lh1 * 7;
    const float* m0p = mask + (size_t)win * (L_TOK * L_TOK) + l0 * L_TOK;
    const float* m1p = mask + (size_t)win * (L_TOK * L_TOK) + l1 * L_TOK;
    const float scale = 0.1767766952966369f;

    float mx0 = -1e30f, mx1 = -1e30f;
    #pragma unroll
    for (int j = 0; j < 7; ++j) {
        int ma = 8 * j + 2 * t, mb = ma + 1;
        int mha = ma / 7, mwa = ma - mha * 7;
        int mhb = mb / 7, mwb = mb - mhb * 7;
        float* c = sacc[j];
        c[0] = (v0 && ma < L_TOK)
             ? c[0] * scale + sm[AB_OFF + (lh0 - mha + 6) * 13 + (lw0 - mwa + 6)] + m0p[ma]
             : -1e30f;
        c[1] = (v0 && mb < L_TOK)
             ? c[1] * scale + sm[AB_OFF + (lh0 - mhb + 6) * 13 + (lw0 - mwb + 6)] + m0p[mb]
             : -1e30f;
        c[2] = (v1 && ma < L_TOK)
             ? c[2] * scale + sm[AB_OFF + (lh1 - mha + 6) * 13 + (lw1 - mwa + 6)] + m1p[ma]
             : -1e30f;
        c[3] = (v1 && mb < L_TOK)
             ? c[3] * scale + sm[AB_OFF + (lh1 - mhb + 6) * 13 + (lw1 - mwb + 6)] + m1p[mb]
             : -1e30f;
        mx0 = fmaxf(mx0, fmaxf(c[0], c[1]));
        mx1 = fmaxf(mx1, fmaxf(c[2], c[3]));
    }
    mx0 = fmaxf(mx0, __shfl_xor_sync(0xffffffffu, mx0, 1));
    mx0 = fmaxf(mx0, __shfl_xor_sync(0xffffffffu, mx0, 2));
    mx1 = fmaxf(mx1, __shfl_xor_sync(0xffffffffu, mx1, 1));
    mx1 = fmaxf(mx1, __shfl_xor_sync(0xffffffffu, mx1, 2));

    float s0 = 0.f, s1 = 0.f;
    #pragma unroll
    for (int j = 0; j < 7; ++j) {
        float* c = sacc[j];
        c[0] = __expf(c[0] - mx0);
        c[1] = __expf(c[1] - mx0);
        c[2] = __expf(c[2] - mx1);
        c[3] = __expf(c[3] - mx1);
        s0 += c[0] + c[1];
        s1 += c[2] + c[3];
    }
    s0 += __shfl_xor_sync(0xffffffffu, s0, 1);
    s0 += __shfl_xor_sync(0xffffffffu, s0, 2);
    s1 += __shfl_xor_sync(0xffffffffu, s1, 1);
    s1 += __shfl_xor_sync(0xffffffffu, s1, 2);
    const float i0 = 1.f / s0, i1 = 1.f / s1;

    // P -> smem S (tf32-rounded for the PV mma)
    #pragma unroll
    for (int j = 0; j < 7; ++j) {
        float* c = sacc[j];
        int col = 8 * j + 2 * t;
        *(float2*)&sm[AS_OFF + l0 * 68 + col] =
            make_float2(f2tf32(c[0] * i0), f2tf32(c[1] * i0));
        *(float2*)&sm[AS_OFF + l1 * 68 + col] =
            make_float2(f2tf32(c[2] * i1), f2tf32(c[3] * i1));
    }
    __syncwarp();   // each warp reads back only its own 16 rows

    // ---- O = P @ V ----
    float oacc[4][4];
    #pragma unroll
    for (int nt = 0; nt < 4; ++nt)
        #pragma unroll
        for (int r = 0; r < 4; ++r) oacc[nt][r] = 0.f;

    #pragma unroll
    for (int ks = 0; ks < 7; ++ks) {
        uint32_t a[4];
        ldsm_x4(sbase + AS_OFF * 4 +
                (uint32_t)((aRow * 17 + (2 * ks + aCol)) * 16),
                a[0], a[1], a[2], a[3]);
        uint32_t bf[2][4];
        #pragma unroll
        for (int ntp = 0; ntp < 2; ++ntp) {
            int row = bRowB + ntp * 16;
            ldsm_x4(sbase + AV_OFF * 4 +
                    (uint32_t)((row * 16 + ((2 * ks + bHalf) ^ (row & 7))) * 16),
                    bf[ntp][0], bf[ntp][1], bf[ntp][2], bf[ntp][3]);
        }
        #pragma unroll
        for (int nt = 0; nt < 4; ++nt)
            MMA_TF32(oacc[nt], a[0], a[1], a[2], a[3],
                     bf[nt >> 1][(nt & 1) * 2], bf[nt >> 1][(nt & 1) * 2 + 1]);
    }

    // ---- write merged-head output ----
    float* orow0 = out + ((size_t)b * L_TOK + l0) * C_DIM + h * HD_DIM;
    float* orow1 = orow0 + (size_t)8 * C_DIM;
    #pragma unroll
    for (int nt = 0; nt < 4; ++nt) {
        int d = nt * 8 + t * 2;
        if (v0) *(float2*)(orow0 + d) = make_float2(oacc[nt][0], oacc[nt][1]);
        if (v1) *(float2*)(orow1 + d) = make_float2(oacc[nt][2], oacc[nt][3]);
    }
}

// ---------------------------------------------------------------------------
// kernel_launch
// ---------------------------------------------------------------------------
extern "C" void kernel_launch(void* const* d_in, const int* in_sizes, int n_in,
                              void* d_out, int out_size) {
    const float* x     = (const float*)d_in[0];
    const float* mask  = (const float*)d_in[1];
    const float* bias  = (const float*)d_in[2];
    const float* wqkv  = (const float*)d_in[3];
    const float* wproj = (const float*)d_in[4];
    float*       out   = (float*)d_out;

    float *qkv = nullptr, *att = nullptr, *wqkv_t = nullptr, *wproj_t = nullptr;
    cudaGetSymbolAddress((void**)&qkv, g_qkv);
    cudaGetSymbolAddress((void**)&att, g_att);
    cudaGetSymbolAddress((void**)&wqkv_t, g_wqkv_t);
    cudaGetSymbolAddress((void**)&wproj_t, g_wproj_t);

    // 0) Transpose weights to n-major for ldmatrix-friendly B tiles
    transpose_k<<<dim3(1536 / 32, 512 / 32), dim3(32, 8)>>>(wqkv, wqkv_t, C_DIM, 3 * C_DIM);
    transpose_k<<<dim3(512 / 32, 512 / 32), dim3(32, 8)>>>(wproj, wproj_t, C_DIM, C_DIM);

    // 1) QKV projection: [100352, 512] x [512, 1536]
    gemm_tf32<<<dim3(1536 / 128, ROWS / 128), 256>>>(x, wqkv_t, qkv, ROWS, 3 * C_DIM, C_DIM);

    // 2) Windowed attention (tensor cores), per (window, head)
    attn_tc<<<dim3(B_TOT, H_HEADS), 128>>>(qkv, mask, bias, att);

    // 3) Output projection: [100352, 512] x [512, 512]
    gemm_tf32<<<dim3(C_DIM / 128, ROWS / 128), 256>>>(att, wproj_t, out, ROWS, C_DIM, C_DIM);
}

// round 6
// speedup vs baseline: 3.7191x; 1.1638x over previous
#include <cuda_runtime.h>
#include <math.h>
#include <stdint.h>

// ---------------------------------------------------------------------------
// Problem constants
// ---------------------------------------------------------------------------
#define B_TOT   2048
#define L_TOK   49
#define C_DIM   512
#define H_HEADS 16
#define HD_DIM  32
#define ROWS    (B_TOT * L_TOK)        // 100352 = 784 * 128

// Scratch (device globals; allocation-free per harness rules)
static __device__ float g_qkv[(size_t)ROWS * 3 * C_DIM];   // 616 MB
static __device__ float g_att[(size_t)ROWS * C_DIM];       // 205 MB
static __device__ float g_xr[(size_t)ROWS * C_DIM];        // 205 MB (tf32-rounded x)
static __device__ float g_wqkv_t[3 * C_DIM * C_DIM];
static __device__ float g_wproj_t[C_DIM * C_DIM];
static __device__ float g_bm[64 * 16 * 49 * 56];           // bias+mask combined, 11.2 MB

__device__ __forceinline__ float f2tf32(float x) {
    unsigned u;
    asm("cvt.rna.tf32.f32 %0, %1;" : "=r"(u) : "f"(x));
    return __uint_as_float(u);
}

__device__ __forceinline__ void ldsm_x4(uint32_t addr, uint32_t& r0, uint32_t& r1,
                                        uint32_t& r2, uint32_t& r3) {
    asm volatile("ldmatrix.sync.aligned.m8n8.x4.shared.b16 {%0,%1,%2,%3}, [%4];"
                 : "=r"(r0), "=r"(r1), "=r"(r2), "=r"(r3) : "r"(addr));
}

__device__ __forceinline__ void cp_async16(uint32_t smem_addr, const void* gptr) {
    asm volatile("cp.async.cg.shared.global [%0], [%1], 16;\n"
                 :: "r"(smem_addr), "l"(gptr) : "memory");
}

#define CP_COMMIT() asm volatile("cp.async.commit_group;\n" ::: "memory")

#define MMA_TF32(c, a0, a1, a2, a3, b0, b1)                                     \
    asm volatile(                                                               \
        "mma.sync.aligned.m16n8k8.row.col.f32.tf32.tf32.f32 "                   \
        "{%0,%1,%2,%3}, {%4,%5,%6,%7}, {%8,%9}, {%0,%1,%2,%3};\n"               \
        : "+f"((c)[0]), "+f"((c)[1]), "+f"((c)[2]), "+f"((c)[3])                \
        : "r"(a0), "r"(a1), "r"(a2), "r"(a3), "r"(b0), "r"(b1))

// ---------------------------------------------------------------------------
// Pre-pass kernels
// ---------------------------------------------------------------------------
__global__ void round_tf32(const float4* __restrict__ in, float4* __restrict__ out, int n4) {
    int i = blockIdx.x * blockDim.x + threadIdx.x;
    if (i < n4) {
        float4 v = in[i];
        out[i] = make_float4(f2tf32(v.x), f2tf32(v.y), f2tf32(v.z), f2tf32(v.w));
    }
}

// Wt[n][k] = tf32(W[k][n])
__global__ void transpose_k(const float* __restrict__ W, float* __restrict__ Wt,
                            int Kdim, int Ndim) {
    __shared__ float t[32][33];
    const int n0 = blockIdx.x * 32, k0 = blockIdx.y * 32;
    const int x = threadIdx.x, y = threadIdx.y;
    #pragma unroll
    for (int i = 0; i < 32; i += 8)
        t[y + i][x] = W[(size_t)(k0 + y + i) * Ndim + n0 + x];
    __syncthreads();
    #pragma unroll
    for (int i = 0; i < 32; i += 8)
        Wt[(size_t)(n0 + y + i) * Kdim + k0 + x] = f2tf32(t[x][y + i]);
}

// bm[win][h][l][m(pad 56)] = bias_table[rel(l,m)][h] + mask[win][l][m]
__global__ void build_bm(const float* __restrict__ mask, const float* __restrict__ bias,
                         float* __restrict__ bm) {
    int idx = blockIdx.x * 256 + threadIdx.x;
    const int TOT = 64 * 16 * 49 * 56;
    if (idx >= TOT) return;
    int m = idx % 56;
    int r = idx / 56;
    int l = r % 49;
    int wh = r / 49;
    int h = wh % 16;
    int win = wh / 16;
    float v = 0.f;
    if (m < 49) {
        int lh = l / 7, lw = l - lh * 7;
        int mh = m / 7, mw = m - mh * 7;
        int ri = (lh - mh + 6) * 13 + (lw - mw + 6);
        v = bias[ri * 16 + h] + mask[(win * 49 + l) * 49 + m];
    }
    bm[idx] = v;
}

// ---------------------------------------------------------------------------
// tf32 GEMM with cp.async 3-stage pipeline.  C[M,N] = A[M,K] * Bt[N,K]^T
// Inputs must already be tf32-rounded.  BM=BN=128, BK=16, 256 threads.
// ---------------------------------------------------------------------------
__global__ __launch_bounds__(256, 2)
void gemm_tf32(const float* __restrict__ A, const float* __restrict__ Bt,
               float* __restrict__ C, int M, int N, int K) {
    __shared__ float As[3][2048];
    __shared__ float Bs[3][2048];

    const int tid  = threadIdx.x;
    const int lane = tid & 31;
    const int warp = tid >> 5;
    const int wm   = warp >> 2;
    const int wn   = warp & 3;

    const int m0 = blockIdx.y * 128;
    const int n0 = blockIdx.x * 128;

    const int r_g = tid >> 2;
    const int q   = tid & 3;

    const float* Ag  = A  + (size_t)(m0 + r_g) * K + q * 4;
    const float* Ag2 = Ag + (size_t)64 * K;
    const float* Bg  = Bt + (size_t)(n0 + r_g) * K + q * 4;
    const float* Bg2 = Bg + (size_t)64 * K;

    const int st0 = (r_g * 4 + (q ^ ((r_g >> 1) & 3))) * 16;   // BYTES
    const int st1 = st0 + 64 * 4 * 16;

    const int swz   = (lane >> 1) & 3;
    const int aRow  = wm * 64 + (lane & 7) + ((lane >> 3) & 1) * 8;
    const int aCol  = lane >> 4;
    const int bRow  = wn * 32 + (lane & 7) + (lane >> 4) * 8;
    const int bHalf = (lane >> 3) & 1;

    uint32_t asb[3], bsb[3];
    #pragma unroll
    for (int s = 0; s < 3; ++s) {
        asb[s] = (uint32_t)__cvta_generic_to_shared(&As[s][0]);
        bsb[s] = (uint32_t)__cvta_generic_to_shared(&Bs[s][0]);
    }

    float acc[16][4];
    #pragma unroll
    for (int i = 0; i < 16; ++i)
        #pragma unroll
        for (int j = 0; j < 4; ++j) acc[i][j] = 0.f;

    const int nK = K >> 4;

    // Prologue: stages 0, 1
    #pragma unroll
    for (int p = 0; p < 2; ++p) {
        cp_async16(asb[p] + st0, Ag  + p * 16);
        cp_async16(asb[p] + st1, Ag2 + p * 16);
        cp_async16(bsb[p] + st0, Bg  + p * 16);
        cp_async16(bsb[p] + st1, Bg2 + p * 16);
        CP_COMMIT();
    }

    int s = 0;
    for (int kt = 0; kt < nK; ++kt) {
        if (kt + 1 < nK) asm volatile("cp.async.wait_group 1;\n" ::: "memory");
        else             asm volatile("cp.async.wait_group 0;\n" ::: "memory");
        __syncthreads();

        if (kt + 2 < nK) {
            int sn = (s + 2) % 3;
            cp_async16(asb[sn] + st0, Ag  + (kt + 2) * 16);
            cp_async16(asb[sn] + st1, Ag2 + (kt + 2) * 16);
            cp_async16(bsb[sn] + st0, Bg  + (kt + 2) * 16);
            cp_async16(bsb[sn] + st1, Bg2 + (kt + 2) * 16);
            CP_COMMIT();
        }

        const uint32_t aB = asb[s];
        const uint32_t bB = bsb[s];

        #pragma unroll
        for (int kkh = 0; kkh < 2; ++kkh) {
            uint32_t af[4][4];
            #pragma unroll
            for (int mt = 0; mt < 4; ++mt) {
                uint32_t addr = aB + (uint32_t)(((aRow + mt * 16) * 4 +
                                 ((kkh * 2 + aCol) ^ swz)) * 16);
                ldsm_x4(addr, af[mt][0], af[mt][1], af[mt][2], af[mt][3]);
            }
            uint32_t bf[2][4];
            #pragma unroll
            for (int ntp = 0; ntp < 2; ++ntp) {
                uint32_t addr = bB + (uint32_t)(((bRow + ntp * 16) * 4 +
                                 ((kkh * 2 + bHalf) ^ swz)) * 16);
                ldsm_x4(addr, bf[ntp][0], bf[ntp][1], bf[ntp][2], bf[ntp][3]);
            }
            #pragma unroll
            for (int mt = 0; mt < 4; ++mt)
                #pragma unroll
                for (int nt = 0; nt < 4; ++nt)
                    MMA_TF32(acc[mt * 4 + nt],
                             af[mt][0], af[mt][1], af[mt][2], af[mt][3],
                             bf[nt >> 1][(nt & 1) * 2], bf[nt >> 1][(nt & 1) * 2 + 1]);
        }
        s = (s + 1) % 3;
        __syncthreads();
    }

    const int g = lane >> 2;
    const int t = lane & 3;
    #pragma unroll
    for (int mt = 0; mt < 4; ++mt) {
        #pragma unroll
        for (int nt = 0; nt < 4; ++nt) {
            const float* c = acc[mt * 4 + nt];
            int row = m0 + wm * 64 + mt * 16 + g;
            int col = n0 + wn * 32 + nt * 8 + t * 2;
            *(float2*)&C[(size_t)row * N + col]       = make_float2(c[0], c[1]);
            *(float2*)&C[(size_t)(row + 8) * N + col] = make_float2(c[2], c[3]);
        }
    }
}

// ---------------------------------------------------------------------------
// Tensor-core attention. One CTA per (window b, head h); 128 threads, 4 warps.
// Smem (floats, 6144 total = 24.6 KB):
//   Qs [64][8 f4]  swizzled, OFF 0       } S [64][15 f4] overlays [0,3840)
//   Ks [64][8 f4]  swizzled, OFF 2048    }   after QK phase
//   Vt [32][16 f4] swizzled, OFF 4096
// Output rounded to tf32 for the following proj GEMM.
// ---------------------------------------------------------------------------
#define AQ_OFF 0
#define AK_OFF 2048
#define AV_OFF 4096
#define ASM_TOT 6144

__global__ __launch_bounds__(128, 6)
void attn_tc(const float* __restrict__ qkv, const float* __restrict__ bm,
             float* __restrict__ out) {
    __shared__ float sm[ASM_TOT];

    const int b = blockIdx.x, h = blockIdx.y;
    const int tid = threadIdx.x, lane = tid & 31, w = tid >> 5;

    const float* base = qkv + (size_t)b * L_TOK * 1536 + h * HD_DIM;

    // Phase 1: Q,K (tf32-rounded, zero-padded) into swizzled smem; zero Vt
    for (int i = tid; i < 512; i += 128) {
        int l = i >> 3, c4 = i & 7;
        float4 z = make_float4(0.f, 0.f, 0.f, 0.f);
        float4 qv = z, kv = z;
        if (l < L_TOK) {
            const float* p = base + (size_t)l * 1536 + c4 * 4;
            float4 qr = *(const float4*)p;
            float4 kr = *(const float4*)(p + C_DIM);
            qv = make_float4(f2tf32(qr.x), f2tf32(qr.y), f2tf32(qr.z), f2tf32(qr.w));
            kv = make_float4(f2tf32(kr.x), f2tf32(kr.y), f2tf32(kr.z), f2tf32(kr.w));
        }
        int dst = (l * 8 + (c4 ^ (l & 7))) * 4;
        *(float4*)&sm[AQ_OFF + dst] = qv;
        *(float4*)&sm[AK_OFF + dst] = kv;
        *(float4*)&sm[AV_OFF + i * 4] = z;
    }
    __syncthreads();

    // Phase 2: V transpose into Vt
    for (int i = tid; i < L_TOK * 8; i += 128) {
        int l = i >> 3, c4 = i & 7;
        float4 v = *(const float4*)(base + (size_t)l * 1536 + 2 * C_DIM + c4 * 4);
        int cl = l >> 2, lo = l & 3;
        float vv[4] = {v.x, v.y, v.z, v.w};
        #pragma unroll
        for (int j = 0; j < 4; ++j) {
            int d = c4 * 4 + j;
            sm[AV_OFF + (d * 16 + (cl ^ (d & 7))) * 4 + lo] = f2tf32(vv[j]);
        }
    }
    __syncthreads();

    const uint32_t sbase = (uint32_t)__cvta_generic_to_shared(sm);

    const int aRow  = w * 16 + (lane & 7) + ((lane >> 3) & 1) * 8;
    const int aCol  = lane >> 4;
    const int bRowB = (lane & 7) + (lane >> 4) * 8;
    const int bHalf = (lane >> 3) & 1;

    // ---- QK^T ----
    float sacc[7][4];
    #pragma unroll
    for (int j = 0; j < 7; ++j)
        #pragma unroll
        for (int r = 0; r < 4; ++r) sacc[j][r] = 0.f;

    #pragma unroll
    for (int ks = 0; ks < 4; ++ks) {
        uint32_t a[4];
        ldsm_x4(sbase + AQ_OFF * 4 +
                (uint32_t)((aRow * 8 + ((2 * ks + aCol) ^ (aRow & 7))) * 16),
                a[0], a[1], a[2], a[3]);
        uint32_t bf[4][4];
        #pragma unroll
        for (int ntp = 0; ntp < 4; ++ntp) {
            int row = bRowB + ntp * 16;
            ldsm_x4(sbase + AK_OFF * 4 +
                    (uint32_t)((row * 8 + ((2 * ks + bHalf) ^ (row & 7))) * 16),
                    bf[ntp][0], bf[ntp][1], bf[ntp][2], bf[ntp][3]);
        }
        #pragma unroll
        for (int nt = 0; nt < 7; ++nt)
            MMA_TF32(sacc[nt], a[0], a[1], a[2], a[3],
                     bf[nt >> 1][(nt & 1) * 2], bf[nt >> 1][(nt & 1) * 2 + 1]);
    }

    // ---- scale + (bias+mask) + softmax, register resident ----
    const int g = lane >> 2, t = lane & 3;
    const int l0 = w * 16 + g, l1 = l0 + 8;
    const int win = b & 63;
    const bool v0 = (l0 < L_TOK), v1 = (l1 < L_TOK);
    const int l0c = v0 ? l0 : 48, l1c = v1 ? l1 : 48;
    const float* bm0 = bm + (((size_t)win * 16 + h) * 49 + l0c) * 56;
    const float* bm1 = bm + (((size_t)win * 16 + h) * 49 + l1c) * 56;
    const float scale = 0.1767766952966369f;

    float mx0 = -1e30f, mx1 = -1e30f;
    #pragma unroll
    for (int j = 0; j < 7; ++j) {
        int ma = 8 * j + 2 * t;
        float2 ba = *(const float2*)&bm0[ma];
        float2 bb = *(const float2*)&bm1[ma];
        float* c = sacc[j];
        c[0] = (v0 && ma     < L_TOK) ? fmaf(c[0], scale, ba.x) : -1e30f;
        c[1] = (v0 && ma + 1 < L_TOK) ? fmaf(c[1], scale, ba.y) : -1e30f;
        c[2] = (v1 && ma     < L_TOK) ? fmaf(c[2], scale, bb.x) : -1e30f;
        c[3] = (v1 && ma + 1 < L_TOK) ? fmaf(c[3], scale, bb.y) : -1e30f;
        mx0 = fmaxf(mx0, fmaxf(c[0], c[1]));
        mx1 = fmaxf(mx1, fmaxf(c[2], c[3]));
    }
    mx0 = fmaxf(mx0, __shfl_xor_sync(0xffffffffu, mx0, 1));
    mx0 = fmaxf(mx0, __shfl_xor_sync(0xffffffffu, mx0, 2));
    mx1 = fmaxf(mx1, __shfl_xor_sync(0xffffffffu, mx1, 1));
    mx1 = fmaxf(mx1, __shfl_xor_sync(0xffffffffu, mx1, 2));

    float s0 = 0.f, s1 = 0.f;
    #pragma unroll
    for (int j = 0; j < 7; ++j) {
        float* c = sacc[j];
        c[0] = __expf(c[0] - mx0);
        c[1] = __expf(c[1] - mx0);
        c[2] = __expf(c[2] - mx1);
        c[3] = __expf(c[3] - mx1);
        s0 += c[0] + c[1];
        s1 += c[2] + c[3];
    }
    s0 += __shfl_xor_sync(0xffffffffu, s0, 1);
    s0 += __shfl_xor_sync(0xffffffffu, s0, 2);
    s1 += __shfl_xor_sync(0xffffffffu, s1, 1);
    s1 += __shfl_xor_sync(0xffffffffu, s1, 2);
    const float i0 = 1.f / s0, i1 = 1.f / s1;

    // All warps done reading Q/K -> safe to overlay S onto [0, 3840)
    __syncthreads();

    // P -> S (stride 60 floats = 15 f4; gcd(15,8)=1 -> ldmatrix conflict-free)
    #pragma unroll
    for (int j = 0; j < 7; ++j) {
        float* c = sacc[j];
        int col = 8 * j + 2 * t;
        *(float2*)&sm[l0 * 60 + col] = make_float2(f2tf32(c[0] * i0), f2tf32(c[1] * i0));
        *(float2*)&sm[l1 * 60 + col] = make_float2(f2tf32(c[2] * i1), f2tf32(c[3] * i1));
    }
    __syncwarp();   // each warp reads only its own 16 rows of S

    // ---- O = P @ V ----
    float oacc[4][4];
    #pragma unroll
    for (int nt = 0; nt < 4; ++nt)
        #pragma unroll
        for (int r = 0; r < 4; ++r) oacc[nt][r] = 0.f;

    #pragma unroll
    for (int ks = 0; ks < 7; ++ks) {
        uint32_t a[4];
        ldsm_x4(sbase + (uint32_t)((aRow * 15 + (2 * ks + aCol)) * 16),
                a[0], a[1], a[2], a[3]);
        uint32_t bf[2][4];
        #pragma unroll
        for (int ntp = 0; ntp < 2; ++ntp) {
            int row = bRowB + ntp * 16;
            ldsm_x4(sbase + AV_OFF * 4 +
                    (uint32_t)((row * 16 + ((2 * ks + bHalf) ^ (row & 7))) * 16),
                    bf[ntp][0], bf[ntp][1], bf[ntp][2], bf[ntp][3]);
        }
        #pragma unroll
        for (int nt = 0; nt < 4; ++nt)
            MMA_TF32(oacc[nt], a[0], a[1], a[2], a[3],
                     bf[nt >> 1][(nt & 1) * 2], bf[nt >> 1][(nt & 1) * 2 + 1]);
    }

    // ---- write merged-head output (tf32-rounded for the proj GEMM) ----
    float* orow0 = out + ((size_t)b * L_TOK + l0) * C_DIM + h * HD_DIM;
    float* orow1 = orow0 + (size_t)8 * C_DIM;
    #pragma unroll
    for (int nt = 0; nt < 4; ++nt) {
        int d = nt * 8 + t * 2;
        if (v0) *(float2*)(orow0 + d) = make_float2(f2tf32(oacc[nt][0]), f2tf32(oacc[nt][1]));
        if (v1) *(float2*)(orow1 + d) = make_float2(f2tf32(oacc[nt][2]), f2tf32(oacc[nt][3]));
    }
}

// ---------------------------------------------------------------------------
// kernel_launch
// ---------------------------------------------------------------------------
extern "C" void kernel_launch(void* const* d_in, const int* in_sizes, int n_in,
                              void* d_out, int out_size) {
    const float* x     = (const float*)d_in[0];
    const float* mask  = (const float*)d_in[1];
    const float* bias  = (const float*)d_in[2];
    const float* wqkv  = (const float*)d_in[3];
    const float* wproj = (const float*)d_in[4];
    float*       out   = (float*)d_out;

    float *qkv, *att, *xr, *wqkv_t, *wproj_t, *bm;
    cudaGetSymbolAddress((void**)&qkv, g_qkv);
    cudaGetSymbolAddress((void**)&att, g_att);
    cudaGetSymbolAddress((void**)&xr, g_xr);
    cudaGetSymbolAddress((void**)&wqkv_t, g_wqkv_t);
    cudaGetSymbolAddress((void**)&wproj_t, g_wproj_t);
    cudaGetSymbolAddress((void**)&bm, g_bm);

    // 0) Pre-passes: round x, transpose+round weights, build bias+mask table
    const int n4 = ROWS * C_DIM / 4;
    round_tf32<<<(n4 + 255) / 256, 256>>>((const float4*)x, (float4*)xr, n4);
    transpose_k<<<dim3(1536 / 32, 512 / 32), dim3(32, 8)>>>(wqkv, wqkv_t, C_DIM, 3 * C_DIM);
    transpose_k<<<dim3(512 / 32, 512 / 32), dim3(32, 8)>>>(wproj, wproj_t, C_DIM, C_DIM);
    const int bmTot = 64 * 16 * 49 * 56;
    build_bm<<<(bmTot + 255) / 256, 256>>>(mask, bias, bm);

    // 1) QKV projection
    gemm_tf32<<<dim3(1536 / 128, ROWS / 128), 256>>>(xr, wqkv_t, qkv, ROWS, 3 * C_DIM, C_DIM);

    // 2) Windowed attention (tensor cores)
    attn_tc<<<dim3(B_TOT, H_HEADS), 128>>>(qkv, bm, att);

    // 3) Output projection
    gemm_tf32<<<dim3(C_DIM / 128, ROWS / 128), 256>>>(att, wproj_t, out, ROWS, C_DIM, C_DIM);
}

// round 8
// speedup vs baseline: 5.3484x; 1.4381x over previous
#include <cuda_runtime.h>
#include <cuda_fp16.h>
#include <math.h>
#include <stdint.h>

// ---------------------------------------------------------------------------
// Problem constants
//   x [2048,49,512] f32, mask [64,49,49] f32, bias_tab [169,16] f32,
//   w_qkv [512,1536] f32, w_proj [512,512] f32, out [2048,49,512] f32
// ---------------------------------------------------------------------------
#define B_TOT   2048
#define L_TOK   49
#define C_DIM   512
#define H_HEADS 16
#define HD_DIM  32
#define ROWS    (B_TOT * L_TOK)        // 100352 = 784 * 128

// Scratch (device globals; allocation-free per harness rules). Stored as
// ushort, reinterpreted as __half.
static __device__ unsigned short g_xh[(size_t)ROWS * C_DIM];        // 102 MB
static __device__ unsigned short g_qkvh[(size_t)ROWS * 3 * C_DIM];  // 308 MB
static __device__ unsigned short g_atth[(size_t)ROWS * C_DIM];      // 102 MB
static __device__ unsigned short g_wqkvth[3 * C_DIM * C_DIM];
static __device__ unsigned short g_wprojth[C_DIM * C_DIM];
static __device__ float g_bm[64 * 16 * 49 * 56];                    // 11.2 MB

// ---------------------------------------------------------------------------
// Helpers
// ---------------------------------------------------------------------------
__device__ __forceinline__ uint32_t smem_u32(const void* p) {
    uint32_t a;
    asm("{ .reg .u64 t; cvta.to.shared.u64 t, %1; cvt.u32.u64 %0, t; }" : "=r"(a) : "l"(p));
    return a;
}

__device__ __forceinline__ void ldsm_x4(uint32_t addr, uint32_t& r0, uint32_t& r1,
                                        uint32_t& r2, uint32_t& r3) {
    asm volatile("ldmatrix.sync.aligned.m8n8.x4.shared.b16 {%0,%1,%2,%3}, [%4];"
                 : "=r"(r0), "=r"(r1), "=r"(r2), "=r"(r3) : "r"(addr));
}

__device__ __forceinline__ void cp_async16(uint32_t d, const void* s) {
    asm volatile("cp.async.cg.shared.global [%0], [%1], 16;" :: "r"(d), "l"(s) : "memory");
}
__device__ __forceinline__ void cp_async16z(uint32_t d, const void* s, uint32_t sz) {
    asm volatile("cp.async.cg.shared.global [%0], [%1], 16, %2;"
                 :: "r"(d), "l"(s), "r"(sz) : "memory");
}
#define CP_COMMIT() asm volatile("cp.async.commit_group;" ::: "memory")

// fp16 mma, fp32 accum
#define MMA_F16(c, a0, a1, a2, a3, b0, b1)                                      \
    asm volatile(                                                               \
        "mma.sync.aligned.m16n8k16.row.col.f32.f16.f16.f32 "                    \
        "{%0,%1,%2,%3}, {%4,%5,%6,%7}, {%8,%9}, {%0,%1,%2,%3};\n"               \
        : "+f"((c)[0]), "+f"((c)[1]), "+f"((c)[2]), "+f"((c)[3])                \
        : "r"(a0), "r"(a1), "r"(a2), "r"(a3), "r"(b0), "r"(b1))

// ---------------------------------------------------------------------------
// Pre-pass kernels
// ---------------------------------------------------------------------------
__global__ void f32_to_f16(const float4* __restrict__ in, __half2* __restrict__ out, int n4) {
    int i = blockIdx.x * blockDim.x + threadIdx.x;
    if (i < n4) {
        float4 v = in[i];
        out[2 * i]     = __floats2half2_rn(v.x, v.y);
        out[2 * i + 1] = __floats2half2_rn(v.z, v.w);
    }
}

// Wt[n][k] = f16(W[k][n])
__global__ void transpose_h(const float* __restrict__ W, __half* __restrict__ Wt,
                            int Kdim, int Ndim) {
    __shared__ float t[32][33];
    const int n0 = blockIdx.x * 32, k0 = blockIdx.y * 32;
    const int x = threadIdx.x, y = threadIdx.y;
    #pragma unroll
    for (int i = 0; i < 32; i += 8)
        t[y + i][x] = W[(size_t)(k0 + y + i) * Ndim + n0 + x];
    __syncthreads();
    #pragma unroll
    for (int i = 0; i < 32; i += 8)
        Wt[(size_t)(n0 + y + i) * Kdim + k0 + x] = __float2half_rn(t[x][y + i]);
}

__global__ void build_bm(const float* __restrict__ mask, const float* __restrict__ bias,
                         float* __restrict__ bm) {
    int idx = blockIdx.x * 256 + threadIdx.x;
    const int TOT = 64 * 16 * 49 * 56;
    if (idx >= TOT) return;
    int m = idx % 56;
    int r = idx / 56;
    int l = r % 49;
    int wh = r / 49;
    int h = wh % 16;
    int win = wh / 16;
    float v = 0.f;
    if (m < 49) {
        int lh = l / 7, lw = l - lh * 7;
        int mh = m / 7, mw = m - mh * 7;
        int ri = (lh - mh + 6) * 13 + (lw - mw + 6);
        v = bias[ri * 16 + h] + mask[(win * 49 + l) * 49 + m];
    }
    bm[idx] = v;
}

// ---------------------------------------------------------------------------
// fp16 GEMM: C[M,N] = A[M,K] * Bt[N,K]^T, fp32 accumulate.
// BM=BN=128, BK=32 halves, 3-stage cp.async, 256 threads, 8 warps (2m x 4n),
// warp tile 64x32 via mma.m16n8k16. Stage: A[128][64B] + B[128][64B] = 16 KB.
// Smem rows = [row][4 x 16B units], XOR swizzle unit ^= (row>>1)&3
// (store + ldmatrix conflict-freedom proven in rounds 4/6).
// ---------------------------------------------------------------------------
template <bool OUT_HALF>
__global__ __launch_bounds__(256, 2)
void gemm_h(const __half* __restrict__ A, const __half* __restrict__ Bt,
            void* __restrict__ Cv, int M, int N, int K) {
    __shared__ __align__(16) char smem[3][16384];

    const int tid = threadIdx.x, lane = tid & 31, warp = tid >> 5;
    const int wm = warp >> 2, wn = warp & 3;
    const int m0 = blockIdx.y * 128, n0 = blockIdx.x * 128;

    // cp.async mapping: 2 A-units + 2 B-units per thread
    const int row = tid >> 1;            // 0..127
    const int cb  = (tid & 1) * 2;       // unit 0/2 base
    const __half* ag = A  + (size_t)(m0 + row) * K + cb * 8;
    const __half* bg = Bt + (size_t)(n0 + row) * K + cb * 8;
    const uint32_t sw0 = row * 64 + (((cb)     ^ ((row >> 1) & 3)) << 4);
    const uint32_t sw1 = row * 64 + (((cb + 1) ^ ((row >> 1) & 3)) << 4);

    uint32_t sb[3];
    #pragma unroll
    for (int s = 0; s < 3; ++s) sb[s] = smem_u32(smem[s]);

    // ldmatrix lane constants
    const int rr = lane & 7;
    const int mA = (lane >> 3) & 1;      // +8 row select
    const int kU = lane >> 4;            // k-unit select

    float acc[16][4];
    #pragma unroll
    for (int i = 0; i < 16; ++i)
        #pragma unroll
        for (int j = 0; j < 4; ++j) acc[i][j] = 0.f;

    const int nK = K >> 5;               // 32 halves per tile

    #pragma unroll
    for (int p = 0; p < 2; ++p) {
        cp_async16(sb[p] + sw0, ag + p * 32);
        cp_async16(sb[p] + sw1, ag + p * 32 + 8);
        cp_async16(sb[p] + 8192 + sw0, bg + p * 32);
        cp_async16(sb[p] + 8192 + sw1, bg + p * 32 + 8);
        CP_COMMIT();
    }

    for (int kt = 0; kt < nK; ++kt) {
        if (kt + 1 < nK) asm volatile("cp.async.wait_group 1;" ::: "memory");
        else             asm volatile("cp.async.wait_group 0;" ::: "memory");
        __syncthreads();

        if (kt + 2 < nK) {
            uint32_t so = sb[(kt + 2) % 3];
            cp_async16(so + sw0, ag + (kt + 2) * 32);
            cp_async16(so + sw1, ag + (kt + 2) * 32 + 8);
            cp_async16(so + 8192 + sw0, bg + (kt + 2) * 32);
            cp_async16(so + 8192 + sw1, bg + (kt + 2) * 32 + 8);
            CP_COMMIT();
        }

        const uint32_t aB = sb[kt % 3];
        const uint32_t bB = aB + 8192;

        #pragma unroll
        for (int ks = 0; ks < 2; ++ks) {
            uint32_t af[4][4];
            #pragma unroll
            for (int mt = 0; mt < 4; ++mt) {
                int r = wm * 64 + mt * 16 + mA * 8 + rr;
                int u = ks * 2 + kU;
                ldsm_x4(aB + (uint32_t)(r * 64 + ((u ^ ((r >> 1) & 3)) << 4)),
                        af[mt][0], af[mt][1], af[mt][2], af[mt][3]);
            }
            uint32_t bf[2][4];
            #pragma unroll
            for (int p = 0; p < 2; ++p) {
                int n = wn * 32 + p * 16 + kU * 8 + rr;
                int u = ks * 2 + mA;
                ldsm_x4(bB + (uint32_t)(n * 64 + ((u ^ ((n >> 1) & 3)) << 4)),
                        bf[p][0], bf[p][1], bf[p][2], bf[p][3]);
            }
            #pragma unroll
            for (int mt = 0; mt < 4; ++mt)
                #pragma unroll
                for (int nt = 0; nt < 4; ++nt)
                    MMA_F16(acc[mt * 4 + nt],
                            af[mt][0], af[mt][1], af[mt][2], af[mt][3],
                            bf[nt >> 1][(nt & 1) * 2], bf[nt >> 1][(nt & 1) * 2 + 1]);
        }
        __syncthreads();
    }

    const int g = lane >> 2, t = lane & 3;
    #pragma unroll
    for (int mt = 0; mt < 4; ++mt) {
        #pragma unroll
        for (int nt = 0; nt < 4; ++nt) {
            const float* c = acc[mt * 4 + nt];
            int r = m0 + wm * 64 + mt * 16 + g;
            int cc = n0 + wn * 32 + nt * 8 + t * 2;
            if (OUT_HALF) {
                __half* C = (__half*)Cv;
                *(__half2*)&C[(size_t)r * N + cc]       = __floats2half2_rn(c[0], c[1]);
                *(__half2*)&C[(size_t)(r + 8) * N + cc] = __floats2half2_rn(c[2], c[3]);
            } else {
                float* C = (float*)Cv;
                *(float2*)&C[(size_t)r * N + cc]       = make_float2(c[0], c[1]);
                *(float2*)&C[(size_t)(r + 8) * N + cc] = make_float2(c[2], c[3]);
            }
        }
    }
}

// ---------------------------------------------------------------------------
// fp16 tensor-core attention. One CTA per (window b, head h); 128 thr, 4 warps.
// Smem bytes: Q [64][64B] @0, K [64][64B] @4096, Vt [32][128B] @8192,
//             P [64][144B] @12288  (stride 9 units -> ldmatrix conflict-free).
// ---------------------------------------------------------------------------
#define QO 0
#define KO 4096
#define VO 8192
#define PO 12288
#define ATT_SMEM (12288 + 64 * 144)

__global__ __launch_bounds__(128, 8)
void attn_h(const __half* __restrict__ qkv, const float* __restrict__ bm,
            __half* __restrict__ att) {
    __shared__ __align__(16) char smc[ATT_SMEM];
    const uint32_t sb = smem_u32(smc);

    const int b = blockIdx.x, h = blockIdx.y;
    const int tid = threadIdx.x, lane = tid & 31, w = tid >> 5;

    const __half* base = qkv + (size_t)b * L_TOK * 1536 + h * HD_DIM;

    // Q/K via cp.async (zfill pads rows 49..63); 2 units each per thread
    #pragma unroll
    for (int j = 0; j < 2; ++j) {
        int u = tid * 2 + j;
        int r = u >> 2, c = u & 3;
        uint32_t sz = (r < L_TOK) ? 16u : 0u;
        const __half* qs = (r < L_TOK) ? (base + (size_t)r * 1536 + c * 8) : base;
        const __half* ks = (r < L_TOK) ? (base + (size_t)r * 1536 + 512 + c * 8) : base;
        uint32_t dst = (uint32_t)(r * 64 + ((c ^ ((r >> 1) & 3)) << 4));
        cp_async16z(sb + QO + dst, qs, sz);
        cp_async16z(sb + KO + dst, ks, sz);
    }
    CP_COMMIT();

    // zero Vt (4096 B)
    #pragma unroll
    for (int j = 0; j < 2; ++j)
        *(uint4*)(smc + VO + (tid * 2 + j) * 16) = make_uint4(0, 0, 0, 0);
    __syncthreads();

    // V transpose: V[m][d] -> Vt[d][m]
    for (int i = tid; i < L_TOK * 16; i += 128) {
        int m = i >> 4, d2 = i & 15;
        __half2 v = *(const __half2*)(base + (size_t)m * 1536 + 1024 + d2 * 2);
        int d0 = d2 * 2;
        int u = m >> 3, byo = (2 * m) & 15;
        *(__half*)(smc + VO + d0 * 128 + ((u ^ (d0 & 7)) << 4) + byo)       = __low2half(v);
        *(__half*)(smc + VO + (d0 + 1) * 128 + ((u ^ ((d0 + 1) & 7)) << 4) + byo) = __high2half(v);
    }
    asm volatile("cp.async.wait_group 0;" ::: "memory");
    __syncthreads();

    // ldmatrix lane constants
    const int rr = lane & 7;
    const int mA = (lane >> 3) & 1;
    const int kU = lane >> 4;

    // ---- QK^T: warp w -> rows w*16..+16, cols 0..63 ----
    float sacc[8][4];
    #pragma unroll
    for (int j = 0; j < 8; ++j)
        #pragma unroll
        for (int r = 0; r < 4; ++r) sacc[j][r] = 0.f;

    #pragma unroll
    for (int ks = 0; ks < 2; ++ks) {
        uint32_t a[4];
        {
            int r = w * 16 + mA * 8 + rr;
            int u = ks * 2 + kU;
            ldsm_x4(sb + QO + (uint32_t)(r * 64 + ((u ^ ((r >> 1) & 3)) << 4)),
                    a[0], a[1], a[2], a[3]);
        }
        uint32_t bf[4][4];
        #pragma unroll
        for (int p = 0; p < 4; ++p) {
            int n = p * 16 + kU * 8 + rr;
            int u = ks * 2 + mA;
            ldsm_x4(sb + KO + (uint32_t)(n * 64 + ((u ^ ((n >> 1) & 3)) << 4)),
                    bf[p][0], bf[p][1], bf[p][2], bf[p][3]);
        }
        #pragma unroll
        for (int nt = 0; nt < 8; ++nt)
            MMA_F16(sacc[nt], a[0], a[1], a[2], a[3],
                    bf[nt >> 1][(nt & 1) * 2], bf[nt >> 1][(nt & 1) * 2 + 1]);
    }

    // ---- scale + (bias+mask) + softmax ----
    const int g = lane >> 2, t = lane & 3;
    const int l0 = w * 16 + g, l1 = l0 + 8;
    const int win = b & 63;
    const bool v0 = (l0 < L_TOK), v1 = (l1 < L_TOK);
    const int l0c = v0 ? l0 : 48, l1c = v1 ? l1 : 48;
    const float* bm0 = bm + (((size_t)win * 16 + h) * 49 + l0c) * 56;
    const float* bm1 = bm + (((size_t)win * 16 + h) * 49 + l1c) * 56;
    const float scale = 0.1767766952966369f;

    float mx0 = -1e30f, mx1 = -1e30f;
    #pragma unroll
    for (int j = 0; j < 8; ++j) {
        int ma = 8 * j + 2 * t;
        float* c = sacc[j];
        if (ma < L_TOK) {
            float2 ba = *(const float2*)&bm0[ma];
            float2 bb = *(const float2*)&bm1[ma];
            c[0] = v0 ? fmaf(c[0], scale, ba.x) : -1e30f;
            c[1] = (v0 && ma + 1 < L_TOK) ? fmaf(c[1], scale, ba.y) : -1e30f;
            c[2] = v1 ? fmaf(c[2], scale, bb.x) : -1e30f;
            c[3] = (v1 && ma + 1 < L_TOK) ? fmaf(c[3], scale, bb.y) : -1e30f;
        } else {
            c[0] = c[1] = c[2] = c[3] = -1e30f;
        }
        mx0 = fmaxf(mx0, fmaxf(c[0], c[1]));
        mx1 = fmaxf(mx1, fmaxf(c[2], c[3]));
    }
    mx0 = fmaxf(mx0, __shfl_xor_sync(0xffffffffu, mx0, 1));
    mx0 = fmaxf(mx0, __shfl_xor_sync(0xffffffffu, mx0, 2));
    mx1 = fmaxf(mx1, __shfl_xor_sync(0xffffffffu, mx1, 1));
    mx1 = fmaxf(mx1, __shfl_xor_sync(0xffffffffu, mx1, 2));

    float s0 = 0.f, s1 = 0.f;
    #pragma unroll
    for (int j = 0; j < 8; ++j) {
        float* c = sacc[j];
        c[0] = __expf(c[0] - mx0);
        c[1] = __expf(c[1] - mx0);
        c[2] = __expf(c[2] - mx1);
        c[3] = __expf(c[3] - mx1);
        s0 += c[0] + c[1];
        s1 += c[2] + c[3];
    }
    s0 += __shfl_xor_sync(0xffffffffu, s0, 1);
    s0 += __shfl_xor_sync(0xffffffffu, s0, 2);
    s1 += __shfl_xor_sync(0xffffffffu, s1, 1);
    s1 += __shfl_xor_sync(0xffffffffu, s1, 2);
    const float i0 = 1.f / s0, i1 = 1.f / s1;

    // P -> smem fp16 [64][144B]
    #pragma unroll
    for (int j = 0; j < 8; ++j) {
        float* c = sacc[j];
        int col = 8 * j + 2 * t;
        *(__half2*)(smc + PO + l0 * 144 + col * 2) = __floats2half2_rn(c[0] * i0, c[1] * i0);
        *(__half2*)(smc + PO + l1 * 144 + col * 2) = __floats2half2_rn(c[2] * i1, c[3] * i1);
    }
    __syncwarp();   // each warp reads back only its own rows

    // ---- O = P @ V ----
    float oacc[4][4];
    #pragma unroll
    for (int nt = 0; nt < 4; ++nt)
        #pragma unroll
        for (int r = 0; r < 4; ++r) oacc[nt][r] = 0.f;

    #pragma unroll
    for (int ks = 0; ks < 4; ++ks) {
        uint32_t a[4];
        {
            int r = w * 16 + mA * 8 + rr;
            int u = ks * 2 + kU;
            ldsm_x4(sb + PO + (uint32_t)(r * 144 + u * 16), a[0], a[1], a[2], a[3]);
        }
        uint32_t bf[2][4];
        #pragma unroll
        for (int p = 0; p < 2; ++p) {
            int d = p * 16 + kU * 8 + rr;
            int u = ks * 2 + mA;
            ldsm_x4(sb + VO + (uint32_t)(d * 128 + ((u ^ (d & 7)) << 4)),
                    bf[p][0], bf[p][1], bf[p][2], bf[p][3]);
        }
        #pragma unroll
        for (int nt = 0; nt < 4; ++nt)
            MMA_F16(oacc[nt], a[0], a[1], a[2], a[3],
                    bf[nt >> 1][(nt & 1) * 2], bf[nt >> 1][(nt & 1) * 2 + 1]);
    }

    // ---- write merged-head output (fp16, feeds proj GEMM) ----
    __half* orow0 = att + ((size_t)b * L_TOK + l0) * C_DIM + h * HD_DIM;
    __half* orow1 = orow0 + (size_t)8 * C_DIM;
    #pragma unroll
    for (int nt = 0; nt < 4; ++nt) {
        int d = nt * 8 + t * 2;
        if (v0) *(__half2*)(orow0 + d) = __floats2half2_rn(oacc[nt][0], oacc[nt][1]);
        if (v1) *(__half2*)(orow1 + d) = __floats2half2_rn(oacc[nt][2], oacc[nt][3]);
    }
}

// ---------------------------------------------------------------------------
// kernel_launch
// ---------------------------------------------------------------------------
extern "C" void kernel_launch(void* const* d_in, const int* in_sizes, int n_in,
                              void* d_out, int out_size) {
    const float* x     = (const float*)d_in[0];
    const float* mask  = (const float*)d_in[1];
    const float* bias  = (const float*)d_in[2];
    const float* wqkv  = (const float*)d_in[3];
    const float* wproj = (const float*)d_in[4];
    float*       out   = (float*)d_out;

    void *xh, *qkvh, *atth, *wqkvth, *wprojth, *bm;
    cudaGetSymbolAddress(&xh, g_xh);
    cudaGetSymbolAddress(&qkvh, g_qkvh);
    cudaGetSymbolAddress(&atth, g_atth);
    cudaGetSymbolAddress(&wqkvth, g_wqkvth);
    cudaGetSymbolAddress(&wprojth, g_wprojth);
    cudaGetSymbolAddress(&bm, g_bm);

    // 0) Pre-passes
    const int n4 = ROWS * C_DIM / 4;
    f32_to_f16<<<(n4 + 255) / 256, 256>>>((const float4*)x, (__half2*)xh, n4);
    transpose_h<<<dim3(1536 / 32, 512 / 32), dim3(32, 8)>>>(wqkv, (__half*)wqkvth, C_DIM, 3 * C_DIM);
    transpose_h<<<dim3(512 / 32, 512 / 32), dim3(32, 8)>>>(wproj, (__half*)wprojth, C_DIM, C_DIM);
    const int bmTot = 64 * 16 * 49 * 56;
    build_bm<<<(bmTot + 255) / 256, 256>>>(mask, bias, (float*)bm);

    // 1) QKV projection (fp16 tensor cores, fp32 accum)
    gemm_h<true><<<dim3(1536 / 128, ROWS / 128), 256>>>(
        (const __half*)xh, (const __half*)wqkvth, qkvh, ROWS, 3 * C_DIM, C_DIM);

    // 2) Windowed attention (fp16 tensor cores)
    attn_h<<<dim3(B_TOT, H_HEADS), 128>>>((const __half*)qkvh, (const float*)bm, (__half*)atth);

    // 3) Output projection (fp16 -> fp32 out)
    gemm_h<false><<<dim3(C_DIM / 128, ROWS / 128), 256>>>(
        (const __half*)atth, (const __half*)wprojth, out, ROWS, C_DIM, C_DIM);
}